// round 4
// baseline (speedup 1.0000x reference)
#include <cuda_runtime.h>
#include <cuda_bf16.h>
#include <math.h>

typedef unsigned long long u64;

// Problem constants (fixed by the dataset)
#define BB 2
#define HH 12
#define SS 3456
#define DD 32
#define FPT 216           // feats per timestep
#define NT (SS / FPT)     // 16 timesteps
#define WIN 8
#define IMG_START 20      // FPT - img_feat_size(196)
#define JOINT_START 4     // IMG_START - act_size(16)
#define NPAST 19          // valid past kv_m: {0,1,2,3,5..19}
#define MAXPAST ((WIN - 1) * NPAST)   // 133

// scale * log2(e): ex2.approx(dot) == exp(dot/sqrt(32))
#define SCL2E (0.17677669529663689f * 1.4426950408889634f)

#define THREADS 256       // 216 mains + 40 B-helpers

// smem layout (bytes)
#define SK_BYTES   (FPT * DD * 4)        // 27648
#define PK_BYTES   (MAXPAST * DD * 4)    // 17024
#define OFF_PK_F   (FPT * DD)            // float offset of pK
#define OFF_VADR_B (SK_BYTES + PK_BYTES) // 44672 (8B aligned)
#define NTAB       (MAXPAST + FPT)       // 349 V-row addresses
#define VADR_BYTES 2816                  // 349*8 padded
#define OFF_PART_B (OFF_VADR_B + VADR_BYTES)  // 47488
#define NPARTS     40
#define PART_STRIDE 17                   // u64 per slot (16 acc + lsum)
#define SMEM_BYTES (OFF_PART_B + NPARTS * PART_STRIDE * 8)  // 52928

__device__ __forceinline__ u64 fma2(u64 a, u64 b, u64 c) {
    u64 d; asm("fma.rn.f32x2 %0, %1, %2, %3;" : "=l"(d) : "l"(a), "l"(b), "l"(c)); return d;
}
__device__ __forceinline__ u64 pack2(float lo, float hi) {
    u64 d; asm("mov.b64 %0, {%1, %2};" : "=l"(d) : "f"(lo), "f"(hi)); return d;
}
__device__ __forceinline__ void unpack2(u64 a, float& lo, float& hi) {
    asm("mov.b64 {%0, %1}, %2;" : "=f"(lo), "=f"(hi) : "l"(a));
}
__device__ __forceinline__ float ex2(float x) {
    float r; asm("ex2.approx.f32 %0, %1;" : "=f"(r) : "f"(x)); return r;
}
__device__ __forceinline__ void prefetchL1(const void* p) {
    asm volatile("prefetch.global.L1 [%0];" :: "l"(p));
}

__global__ void __launch_bounds__(THREADS, 3)
eye_attn_kernel(const float* __restrict__ q,
                const float* __restrict__ k,
                const float* __restrict__ v,
                float* __restrict__ out)
{
    extern __shared__ float smem[];
    float* sK   = smem;
    float* pK   = smem + OFF_PK_F;
    u64*   vadr = (u64*)((char*)smem + OFF_VADR_B);
    u64*   part = (u64*)((char*)smem + OFF_PART_B);

    const int t = blockIdx.x;
    const int h = blockIdx.y;
    const int b = blockIdx.z;
    const int tid = threadIdx.x;

    const size_t bh_base = ((size_t)(b * HH + h)) * SS * DD;
    const float* kg = k + bh_base + (size_t)t * FPT * DD;
    const float* vg = v + bh_base + (size_t)t * FPT * DD;

    // ---- stage same-t K tile into smem (coalesced) ----
    {
        const float4* kg4 = (const float4*)kg;
        float4* sK4 = (float4*)sK;
        #pragma unroll 2
        for (int i = tid; i < FPT * DD / 4; i += THREADS)
            sK4[i] = kg4[i];
    }

    const int npt = (t < WIN - 1) ? t : (WIN - 1);   // # past timesteps
    const int npk = npt * NPAST;                     // # valid past rows

    // ---- stage compacted past K rows ----
    {
        const int ntask = npk * 8;                   // 8 float4 per row
        for (int r4 = tid; r4 < ntask; r4 += THREADS) {
            const int r  = r4 >> 3;
            const int c  = r4 & 7;
            const int dt = r / NPAST + 1;
            const int i  = r - (dt - 1) * NPAST;
            const int m  = (i < 4) ? i : (i + 1);    // skip proprio m==4
            const size_t src = bh_base + ((size_t)(t - dt) * FPT + m) * DD;
            ((float4*)pK)[r * 8 + c] = ((const float4*)(k + src))[c];
        }
    }

    // ---- build V-row address table + prefetch V lines into L1 ----
    // entries [0..132]            : past V rows (compacted)
    // entries [133..133+215]      : same-t V rows 0..215
    for (int i = tid; i < NTAB; i += THREADS) {
        const float* addr;
        bool valid = true;
        if (i < MAXPAST) {
            if (i < npk) {
                const int dt = i / NPAST + 1;
                const int j  = i - (dt - 1) * NPAST;
                const int m  = (j < 4) ? j : (j + 1);
                addr = v + bh_base + ((size_t)(t - dt) * FPT + m) * DD;
            } else { addr = vg; valid = false; }
        } else {
            addr = vg + (size_t)(i - MAXPAST) * DD;
        }
        vadr[i] = (u64)addr;
        if (valid) prefetchL1(addr);   // one 128B line per row
    }

    __syncthreads();

    // ---- roles ----
    // tid 0..215  : main for query `tid`. Phase A (20 same-t keys) + all past keys.
    // tid 216..255: B-helper idx = tid-216; query = idx>>1, half = idx&1;
    //               handles 98 same-t keys [20+half*98, ...) for that query.
    const bool main_ = (tid < FPT);
    const int  bidx  = tid - FPT;
    const int  qrow  = main_ ? tid : (bidx >> 1);

    int nA, bn, tbase;
    const float* kb;
    if (main_) {
        nA = IMG_START; bn = npk; tbase = 0; kb = pK;
    } else {
        const int half = bidx & 1;
        nA = 0; bn = 98; tbase = MAXPAST + IMG_START + half * 98;
        kb = sK + (IMG_START + half * 98) * DD;
    }
    const bool jointPred = main_ && (qrow >= JOINT_START) && (qrow < IMG_START);

    // ---- load q row, pre-scaled by scale*log2e, packed f32x2 ----
    u64 q2[16];
    {
        const float4* qg4 = (const float4*)(q + bh_base + ((size_t)t * FPT + qrow) * DD);
        #pragma unroll
        for (int i = 0; i < 8; i++) {
            float4 x = qg4[i];
            q2[2 * i]     = pack2(x.x * SCL2E, x.y * SCL2E);
            q2[2 * i + 1] = pack2(x.z * SCL2E, x.w * SCL2E);
        }
    }

    u64 acc[16];
    #pragma unroll
    for (int i = 0; i < 16; i++) acc[i] = 0ull;
    float lsum = 0.0f;
    const u64 one2 = pack2(1.0f, 1.0f);

    // one key: K from smem, V from global (L1 broadcast)
    auto doKey = [&](const float* krow, const ulonglong2* vrow, bool valid) {
        const ulonglong2* k2 = (const ulonglong2*)krow;
        u64 sA = 0ull, sB = 0ull, sC = 0ull, sD = 0ull;
        ulonglong2 kk;
        kk = k2[0]; sA = fma2(q2[0],  kk.x, sA); sB = fma2(q2[1],  kk.y, sB);
        kk = k2[1]; sC = fma2(q2[2],  kk.x, sC); sD = fma2(q2[3],  kk.y, sD);
        kk = k2[2]; sA = fma2(q2[4],  kk.x, sA); sB = fma2(q2[5],  kk.y, sB);
        kk = k2[3]; sC = fma2(q2[6],  kk.x, sC); sD = fma2(q2[7],  kk.y, sD);
        kk = k2[4]; sA = fma2(q2[8],  kk.x, sA); sB = fma2(q2[9],  kk.y, sB);
        kk = k2[5]; sC = fma2(q2[10], kk.x, sC); sD = fma2(q2[11], kk.y, sD);
        kk = k2[6]; sA = fma2(q2[12], kk.x, sA); sB = fma2(q2[13], kk.y, sB);
        kk = k2[7]; sC = fma2(q2[14], kk.x, sC); sD = fma2(q2[15], kk.y, sD);
        u64 sAB = fma2(sA, one2, sB);
        u64 sCD = fma2(sC, one2, sD);
        u64 sT  = fma2(sAB, one2, sCD);
        float lo, hi; unpack2(sT, lo, hi);
        float e = ex2(lo + hi);
        float p = valid ? e : 0.0f;
        lsum += p;
        u64 p2 = pack2(p, p);
        ulonglong2 vv;
        vv = __ldg(vrow + 0); acc[0]  = fma2(p2, vv.x, acc[0]);  acc[1]  = fma2(p2, vv.y, acc[1]);
        vv = __ldg(vrow + 1); acc[2]  = fma2(p2, vv.x, acc[2]);  acc[3]  = fma2(p2, vv.y, acc[3]);
        vv = __ldg(vrow + 2); acc[4]  = fma2(p2, vv.x, acc[4]);  acc[5]  = fma2(p2, vv.y, acc[5]);
        vv = __ldg(vrow + 3); acc[6]  = fma2(p2, vv.x, acc[6]);  acc[7]  = fma2(p2, vv.y, acc[7]);
        vv = __ldg(vrow + 4); acc[8]  = fma2(p2, vv.x, acc[8]);  acc[9]  = fma2(p2, vv.y, acc[9]);
        vv = __ldg(vrow + 5); acc[10] = fma2(p2, vv.x, acc[10]); acc[11] = fma2(p2, vv.y, acc[11]);
        vv = __ldg(vrow + 6); acc[12] = fma2(p2, vv.x, acc[12]); acc[13] = fma2(p2, vv.y, acc[13]);
        vv = __ldg(vrow + 7); acc[14] = fma2(p2, vv.x, acc[14]); acc[15] = fma2(p2, vv.y, acc[15]);
    };

    // Phase A: same-t keys 0..19 (mains only; helper lanes skip)
    for (int j = 0; j < nA; j++)
        doKey(sK + j * DD, (const ulonglong2*)(vg + (size_t)j * DD), true);

    // Bulk phase: mains -> past keys; helpers -> same-t img-window keys.
    {
        int iw = 0;
        #pragma unroll 2
        for (int r = 0; r < bn; r++) {
            const float* krow = kb + (size_t)r * DD;
            const ulonglong2* vrow = (const ulonglong2*)vadr[tbase + r];
            const bool valid = !jointPred || (iw < 4);
            doKey(krow, vrow, valid);
            if (++iw == NPAST) iw = 0;
        }
    }

    // helpers publish partials
    if (!main_) {
        u64* pp = part + bidx * PART_STRIDE;
        #pragma unroll
        for (int i = 0; i < 16; i++) pp[i] = acc[i];
        ((float*)pp)[32] = lsum;
    }

    __syncthreads();

    if (main_) {
        if (tid < IMG_START) {
            // queries 0..19: add the two B-helper partials (same-t keys 20..215)
            #pragma unroll
            for (int hB = 0; hB < 2; hB++) {
                u64* pp = part + (2 * tid + hB) * PART_STRIDE;
                #pragma unroll
                for (int i = 0; i < 16; i++) acc[i] = fma2(pp[i], one2, acc[i]);
                lsum += ((float*)pp)[32];
            }
        }
        // ---- write out ----
        const float inv = 1.0f / lsum;
        float4* og4 = (float4*)(out + bh_base + ((size_t)t * FPT + tid) * DD);
        #pragma unroll
        for (int i = 0; i < 8; i++) {
            float a0, a1, a2, a3;
            unpack2(acc[2 * i], a0, a1);
            unpack2(acc[2 * i + 1], a2, a3);
            float4 o;
            o.x = a0 * inv; o.y = a1 * inv; o.z = a2 * inv; o.w = a3 * inv;
            og4[i] = o;
        }
    }
}

extern "C" void kernel_launch(void* const* d_in, const int* in_sizes, int n_in,
                              void* d_out, int out_size)
{
    const float* q = (const float*)d_in[0];
    const float* k = (const float*)d_in[1];
    const float* v = (const float*)d_in[2];
    float* out = (float*)d_out;

    cudaFuncSetAttribute(eye_attn_kernel,
                         cudaFuncAttributeMaxDynamicSharedMemorySize, SMEM_BYTES);

    dim3 grid(NT, HH, BB);   // (16, 12, 2)
    eye_attn_kernel<<<grid, THREADS, SMEM_BYTES>>>(q, k, v, out);
}

// round 5
// speedup vs baseline: 2.4700x; 2.4700x over previous
#include <cuda_runtime.h>
#include <cuda_bf16.h>
#include <math.h>

typedef unsigned long long u64;

// Problem constants (fixed by the dataset)
#define BB 2
#define HH 12
#define SS 3456
#define DD 32
#define FPT 216           // feats per timestep
#define NT (SS / FPT)     // 16 timesteps
#define WIN 8
#define IMG_START 20      // FPT - img_feat_size(196)
#define JOINT_START 4     // IMG_START - act_size(16)
#define NPAST 19          // valid past kv_m: {0,1,2,3,5..19}
#define MAXPAST ((WIN - 1) * NPAST)   // 133

// scale * log2(e): ex2.approx(dot) == exp(dot/sqrt(32))
#define SCL2E (0.17677669529663689f * 1.4426950408889634f)

#define THREADS 320       // 216 mains + 40 B-helpers + 64 C-helpers

// smem layout (floats / bytes)
#define OFF_SK 0
#define OFF_SV (FPT * DD)                      // 6912
#define OFF_PK (2 * FPT * DD)                  // 13824
#define OFF_PV (2 * FPT * DD + MAXPAST * DD)   // 18080
#define TILE_FLOATS (2 * FPT * DD + 2 * MAXPAST * DD)  // 22336
#define TILE_BYTES (TILE_FLOATS * 4)           // 89344 (8B aligned)
#define NPARTS 104                              // 40 B + 64 C
#define PART_U64 17                             // 16 acc(u64) + lsum
#define SMEM_BYTES (TILE_BYTES + NPARTS * PART_U64 * 8)  // 103488

__device__ __forceinline__ u64 fma2(u64 a, u64 b, u64 c) {
    u64 d; asm("fma.rn.f32x2 %0, %1, %2, %3;" : "=l"(d) : "l"(a), "l"(b), "l"(c)); return d;
}
__device__ __forceinline__ u64 pack2(float lo, float hi) {
    u64 d; asm("mov.b64 %0, {%1, %2};" : "=l"(d) : "f"(lo), "f"(hi)); return d;
}
__device__ __forceinline__ void unpack2(u64 a, float& lo, float& hi) {
    asm("mov.b64 {%0, %1}, %2;" : "=f"(lo), "=f"(hi) : "l"(a));
}
__device__ __forceinline__ float ex2(float x) {
    float r; asm("ex2.approx.f32 %0, %1;" : "=f"(r) : "f"(x)); return r;
}

__global__ void __launch_bounds__(THREADS, 2)
eye_attn_kernel(const float* __restrict__ q,
                const float* __restrict__ k,
                const float* __restrict__ v,
                float* __restrict__ out)
{
    extern __shared__ float smem[];
    float* sK = smem + OFF_SK;
    float* sV = smem + OFF_SV;
    float* pK = smem + OFF_PK;
    float* pV = smem + OFF_PV;
    u64*   part = (u64*)((char*)smem + TILE_BYTES);

    const int t = blockIdx.x;
    const int h = blockIdx.y;
    const int b = blockIdx.z;
    const int tid = threadIdx.x;

    const size_t bh_base = ((size_t)(b * HH + h)) * SS * DD;

    // ---- stage same-t K/V tiles (contiguous, coalesced) ----
    {
        const float4* kg4 = (const float4*)(k + bh_base + (size_t)t * FPT * DD);
        const float4* vg4 = (const float4*)(v + bh_base + (size_t)t * FPT * DD);
        float4* sK4 = (float4*)sK;
        float4* sV4 = (float4*)sV;
        #pragma unroll 2
        for (int i = tid; i < FPT * DD / 4; i += THREADS) {
            sK4[i] = kg4[i];
            sV4[i] = vg4[i];
        }
    }

    const int npt = (t < WIN - 1) ? t : (WIN - 1);   // # past timesteps
    const int npk = npt * NPAST;                     // # valid past rows
    const int n4  = npt * 4;                         // # joint-visible past rows

    // ---- stage compacted past K/V rows, JOINT-FIRST order ----
    // rows [0, n4)      : (dt, m) with m in {0,1,2,3}   (visible to all queries)
    // rows [n4, npk)    : (dt, m) with m in {5..19}     (invisible to joint queries)
    {
        const int ntask = npk * 8;                   // 8 float4 per row
        for (int r4 = tid; r4 < ntask; r4 += THREADS) {
            const int r = r4 >> 3;
            const int c = r4 & 7;
            int dt, m;
            if (r < n4) { dt = (r >> 2) + 1;          m = r & 3; }
            else        { const int r2 = r - n4;
                          dt = r2 / 15 + 1;           m = 5 + r2 - (dt - 1) * 15; }
            const size_t src = bh_base + ((size_t)(t - dt) * FPT + m) * DD;
            ((float4*)pK)[r * 8 + c] = ((const float4*)(k + src))[c];
            ((float4*)pV)[r * 8 + c] = ((const float4*)(v + src))[c];
        }
    }

    __syncthreads();

    // ---- roles ----
    // tid   0..215 : main for query tid.  Phase A = same-t keys 0..19 (all queries).
    //                Bulk: queries 64..215 do their own past rows [0, npk).
    //                Queries 0..63 have past delegated to C-helpers.
    //                Queries 0..19 have same-t keys 20..215 delegated to B-helpers.
    // tid 216..255 : B-helper idx=tid-216; query=idx>>1, half=idx&1 -> 98 same-t keys.
    // tid 256..319 : C-helper for query tid-256 (0..63): past rows, bound npk or n4.
    const bool main_ = (tid < FPT);
    const bool is_b  = (tid >= FPT) && (tid < FPT + 40);
    const int  bidx  = tid - FPT;
    const int  cidx  = tid - (FPT + 40);

    int qrow;
    if (main_)      qrow = tid;
    else if (is_b)  qrow = bidx >> 1;
    else            qrow = cidx;

    const bool qjoint = (qrow >= JOINT_START) && (qrow < IMG_START);

    // per-thread bulk task: (key base, value base, count)
    const float* kb; const float* vb; int bn; int nA;
    if (main_) {
        nA = IMG_START;
        kb = pK; vb = pV;
        bn = (tid < 64) ? 0 : npk;                     // q0..63 delegated to C
    } else if (is_b) {
        nA = 0;
        const int half = bidx & 1;
        kb = sK + (IMG_START + half * 98) * DD;
        vb = sV + (IMG_START + half * 98) * DD;
        bn = 98;
    } else {
        nA = 0;
        kb = pK; vb = pV;
        bn = qjoint ? n4 : npk;                        // branch-free via layout
    }

    // ---- load q row, pre-scaled by scale*log2e, packed f32x2 ----
    u64 q2[16];
    {
        const float4* qg4 = (const float4*)(q + bh_base + ((size_t)t * FPT + qrow) * DD);
        #pragma unroll
        for (int i = 0; i < 8; i++) {
            float4 x = qg4[i];
            q2[2 * i]     = pack2(x.x * SCL2E, x.y * SCL2E);
            q2[2 * i + 1] = pack2(x.z * SCL2E, x.w * SCL2E);
        }
    }

    u64 acc[16];
    #pragma unroll
    for (int i = 0; i < 16; i++) acc[i] = 0ull;
    float lsum = 0.0f;
    const u64 one2 = pack2(1.0f, 1.0f);

    // one key step: K/V rows from smem (warp-broadcast), no predicates
    auto doKey = [&](const float* krow, const float* vrow) {
        const ulonglong2* k2 = (const ulonglong2*)krow;
        u64 sA = 0ull, sB = 0ull, sC = 0ull, sD = 0ull;
        ulonglong2 kk;
        kk = k2[0]; sA = fma2(q2[0],  kk.x, sA); sB = fma2(q2[1],  kk.y, sB);
        kk = k2[1]; sC = fma2(q2[2],  kk.x, sC); sD = fma2(q2[3],  kk.y, sD);
        kk = k2[2]; sA = fma2(q2[4],  kk.x, sA); sB = fma2(q2[5],  kk.y, sB);
        kk = k2[3]; sC = fma2(q2[6],  kk.x, sC); sD = fma2(q2[7],  kk.y, sD);
        kk = k2[4]; sA = fma2(q2[8],  kk.x, sA); sB = fma2(q2[9],  kk.y, sB);
        kk = k2[5]; sC = fma2(q2[10], kk.x, sC); sD = fma2(q2[11], kk.y, sD);
        kk = k2[6]; sA = fma2(q2[12], kk.x, sA); sB = fma2(q2[13], kk.y, sB);
        kk = k2[7]; sC = fma2(q2[14], kk.x, sC); sD = fma2(q2[15], kk.y, sD);
        u64 sAB = fma2(sA, one2, sB);
        u64 sCD = fma2(sC, one2, sD);
        u64 sT  = fma2(sAB, one2, sCD);
        float lo, hi; unpack2(sT, lo, hi);
        const float p = ex2(lo + hi);
        lsum += p;
        const u64 p2 = pack2(p, p);
        const ulonglong2* v2 = (const ulonglong2*)vrow;
        ulonglong2 vv;
        vv = v2[0]; acc[0]  = fma2(p2, vv.x, acc[0]);  acc[1]  = fma2(p2, vv.y, acc[1]);
        vv = v2[1]; acc[2]  = fma2(p2, vv.x, acc[2]);  acc[3]  = fma2(p2, vv.y, acc[3]);
        vv = v2[2]; acc[4]  = fma2(p2, vv.x, acc[4]);  acc[5]  = fma2(p2, vv.y, acc[5]);
        vv = v2[3]; acc[6]  = fma2(p2, vv.x, acc[6]);  acc[7]  = fma2(p2, vv.y, acc[7]);
        vv = v2[4]; acc[8]  = fma2(p2, vv.x, acc[8]);  acc[9]  = fma2(p2, vv.y, acc[9]);
        vv = v2[5]; acc[10] = fma2(p2, vv.x, acc[10]); acc[11] = fma2(p2, vv.y, acc[11]);
        vv = v2[6]; acc[12] = fma2(p2, vv.x, acc[12]); acc[13] = fma2(p2, vv.y, acc[13]);
        vv = v2[7]; acc[14] = fma2(p2, vv.x, acc[14]); acc[15] = fma2(p2, vv.y, acc[15]);
    };

    // Phase A: same-t keys 0..19 (mains only; helper warps skip uniformly)
    #pragma unroll 2
    for (int j = 0; j < nA; j++)
        doKey(sK + j * DD, sV + j * DD);

    // Bulk phase: branch-free, per-lane base/bound
    #pragma unroll 2
    for (int r = 0; r < bn; r++)
        doKey(kb + r * DD, vb + r * DD);

    // helpers publish partials
    if (!main_) {
        const int slot = is_b ? bidx : (40 + cidx);
        u64* pp = part + slot * PART_U64;
        #pragma unroll
        for (int i = 0; i < 16; i++) pp[i] = acc[i];
        ((float*)pp)[32] = lsum;
    }

    __syncthreads();

    if (main_) {
        if (tid < 64) {
            // add C-helper partial (past keys)
            u64* pp = part + (40 + tid) * PART_U64;
            #pragma unroll
            for (int i = 0; i < 16; i++) acc[i] = fma2(pp[i], one2, acc[i]);
            lsum += ((float*)pp)[32];
        }
        if (tid < IMG_START) {
            // add the two B-helper partials (same-t keys 20..215)
            #pragma unroll
            for (int hB = 0; hB < 2; hB++) {
                u64* pp = part + (2 * tid + hB) * PART_U64;
                #pragma unroll
                for (int i = 0; i < 16; i++) acc[i] = fma2(pp[i], one2, acc[i]);
                lsum += ((float*)pp)[32];
            }
        }
        // ---- write out ----
        const float inv = 1.0f / lsum;
        float4* og4 = (float4*)(out + bh_base + ((size_t)t * FPT + tid) * DD);
        #pragma unroll
        for (int i = 0; i < 8; i++) {
            float a0, a1, a2, a3;
            unpack2(acc[2 * i], a0, a1);
            unpack2(acc[2 * i + 1], a2, a3);
            float4 o;
            o.x = a0 * inv; o.y = a1 * inv; o.z = a2 * inv; o.w = a3 * inv;
            og4[i] = o;
        }
    }
}

extern "C" void kernel_launch(void* const* d_in, const int* in_sizes, int n_in,
                              void* d_out, int out_size)
{
    const float* q = (const float*)d_in[0];
    const float* k = (const float*)d_in[1];
    const float* v = (const float*)d_in[2];
    float* out = (float*)d_out;

    cudaFuncSetAttribute(eye_attn_kernel,
                         cudaFuncAttributeMaxDynamicSharedMemorySize, SMEM_BYTES);

    dim3 grid(NT, HH, BB);   // (16, 12, 2)
    eye_attn_kernel<<<grid, THREADS, SMEM_BYTES>>>(q, k, v, out);
}